// round 1
// baseline (speedup 1.0000x reference)
#include <cuda_runtime.h>
#include <cuda_bf16.h>

#define B_ROWS 65536
#define DIM    256
#define NEMB   1024

#define TM 128
#define TN 128
#define TK 32

// Scratch (allocation-free: __device__ globals)
__device__ unsigned long long g_best[B_ROWS];
__device__ float g_xnorm[B_ROWS];
__device__ float g_enorm[NEMB];

// ---------------------------------------------------------------------------
// Kernel 1a: per-row |x|^2 and reinit of g_best (must happen every launch for
// graph replay determinism).
// ---------------------------------------------------------------------------
__global__ void row_norms_kernel(const float* __restrict__ x) {
    int warp = (blockIdx.x * blockDim.x + threadIdx.x) >> 5;
    int lane = threadIdx.x & 31;
    if (warp >= B_ROWS) return;
    const float4* xr = (const float4*)(x + (size_t)warp * DIM);
    float s = 0.f;
#pragma unroll
    for (int i = lane; i < DIM / 4; i += 32) {
        float4 v = xr[i];
        s += v.x * v.x + v.y * v.y + v.z * v.z + v.w * v.w;
    }
#pragma unroll
    for (int o = 16; o; o >>= 1) s += __shfl_xor_sync(0xFFFFFFFFu, s, o);
    if (lane == 0) {
        g_xnorm[warp] = s;
        g_best[warp]  = 0xFFFFFFFFFFFFFFFFULL;
    }
}

// ---------------------------------------------------------------------------
// Kernel 1b: per-embedding |e|^2
// ---------------------------------------------------------------------------
__global__ void emb_norms_kernel(const float* __restrict__ e) {
    int warp = (blockIdx.x * blockDim.x + threadIdx.x) >> 5;
    int lane = threadIdx.x & 31;
    if (warp >= NEMB) return;
    const float4* er = (const float4*)(e + (size_t)warp * DIM);
    float s = 0.f;
#pragma unroll
    for (int i = lane; i < DIM / 4; i += 32) {
        float4 v = er[i];
        s += v.x * v.x + v.y * v.y + v.z * v.z + v.w * v.w;
    }
#pragma unroll
    for (int o = 16; o; o >>= 1) s += __shfl_xor_sync(0xFFFFFFFFu, s, o);
    if (lane == 0) g_enorm[warp] = s;
}

// ---------------------------------------------------------------------------
// Kernel 2: fused fp32 GEMM (dot(x_m, e_n)) + argmin over distances.
// CTA tile: 128 rows x 128 embeddings, K-chunk 32. 256 threads, 8x8 per thread.
// Distance key packed as (float_bits(d) << 32) | emb_idx; d >= 0 so float bits
// are monotonic; min over key gives min distance with first-index tie-break
// (matches jnp.argmin).
// ---------------------------------------------------------------------------
__global__ __launch_bounds__(256, 2) void gemm_argmin_kernel(
    const float* __restrict__ A,   // inputs  [B_ROWS, DIM]
    const float* __restrict__ E)   // codebook [NEMB, DIM]
{
    __shared__ float As[TK][TM + 1];  // +1 pad: conflict-free transposed stores
    __shared__ float Es[TK][TN + 1];

    const int m0 = blockIdx.x * TM;
    const int n0 = blockIdx.y * TN;
    const int tid = threadIdx.x;
    const int tx = tid & 15;   // 16 threads across N
    const int ty = tid >> 4;   // 16 threads across M

    float acc[8][8];
#pragma unroll
    for (int i = 0; i < 8; i++)
#pragma unroll
        for (int j = 0; j < 8; j++) acc[i][j] = 0.f;

    for (int kt = 0; kt < DIM; kt += TK) {
        // Load 128x32 tiles of A and E (both K-contiguous), transpose into SMEM.
#pragma unroll
        for (int i = 0; i < 4; i++) {
            int f  = tid + i * 256;  // 0..1023 float4 slots
            int r  = f >> 3;         // row within tile
            int c4 = f & 7;          // float4 column within 32-wide k chunk
            float4 va = *(const float4*)(A + (size_t)(m0 + r) * DIM + kt + c4 * 4);
            As[c4 * 4 + 0][r] = va.x;
            As[c4 * 4 + 1][r] = va.y;
            As[c4 * 4 + 2][r] = va.z;
            As[c4 * 4 + 3][r] = va.w;
            float4 ve = *(const float4*)(E + (size_t)(n0 + r) * DIM + kt + c4 * 4);
            Es[c4 * 4 + 0][r] = ve.x;
            Es[c4 * 4 + 1][r] = ve.y;
            Es[c4 * 4 + 2][r] = ve.z;
            Es[c4 * 4 + 3][r] = ve.w;
        }
        __syncthreads();

#pragma unroll
        for (int k = 0; k < TK; k++) {
            float af[8], bf[8];
#pragma unroll
            for (int i = 0; i < 8; i++) af[i] = As[k][ty * 8 + i];
#pragma unroll
            for (int j = 0; j < 8; j++) bf[j] = Es[k][tx * 8 + j];
#pragma unroll
            for (int i = 0; i < 8; i++)
#pragma unroll
                for (int j = 0; j < 8; j++) acc[i][j] = fmaf(af[i], bf[j], acc[i][j]);
        }
        __syncthreads();
    }

    // Epilogue: distances + per-row argmin, reduced across the 16 tx-threads.
    float xn[8], en[8];
#pragma unroll
    for (int i = 0; i < 8; i++) xn[i] = g_xnorm[m0 + ty * 8 + i];
#pragma unroll
    for (int j = 0; j < 8; j++) en[j] = g_enorm[n0 + tx * 8 + j];

#pragma unroll
    for (int i = 0; i < 8; i++) {
        unsigned long long best = 0xFFFFFFFFFFFFFFFFULL;
#pragma unroll
        for (int j = 0; j < 8; j++) {
            float d = fmaxf(xn[i] + en[j] - 2.0f * acc[i][j], 0.0f);
            unsigned long long key =
                ((unsigned long long)__float_as_uint(d) << 32) |
                (unsigned)(n0 + tx * 8 + j);
            best = (key < best) ? key : best;
        }
        // xor-shuffle over the 16 lanes sharing this row (lanes 0-15 / 16-31
        // belong to different ty, xor < 16 stays within the half)
#pragma unroll
        for (int o = 1; o < 16; o <<= 1) {
            unsigned long long other = __shfl_xor_sync(0xFFFFFFFFu, best, o);
            best = (other < best) ? other : best;
        }
        if (tx == 0) atomicMin(&g_best[m0 + ty * 8 + i], best);
    }
}

// ---------------------------------------------------------------------------
// Kernel 3: outputs. One warp per row: loss, quantized_st, one-hot row.
// Output layout: [loss (B*D) | quantized_st (B*D) | onehots (B*K)].
// ---------------------------------------------------------------------------
__global__ void output_kernel(const float* __restrict__ x,
                              const float* __restrict__ Emb,
                              float* __restrict__ out) {
    int warp = (blockIdx.x * blockDim.x + threadIdx.x) >> 5;
    int lane = threadIdx.x & 31;
    if (warp >= B_ROWS) return;
    const int m = warp;
    const unsigned idx = (unsigned)(g_best[m] & 0xFFFFFFFFULL);

    const float4* xr = (const float4*)(x + (size_t)m * DIM);
    const float4* er = (const float4*)(Emb + (size_t)idx * DIM);
    float4* lossp = (float4*)out + (size_t)m * (DIM / 4);
    float4* qp    = (float4*)(out + (size_t)B_ROWS * DIM) + (size_t)m * (DIM / 4);
    float4* ohp   = (float4*)(out + 2ull * B_ROWS * DIM) + (size_t)m * (NEMB / 4);

#pragma unroll
    for (int i = lane; i < DIM / 4; i += 32) {
        float4 xv = xr[i];
        float4 ev = er[i];
        float4 dl, ls, q;
        dl.x = ev.x - xv.x; dl.y = ev.y - xv.y; dl.z = ev.z - xv.z; dl.w = ev.w - xv.w;
        // quantized_st = x + (q - x): same fp op order as the reference
        q.x = xv.x + dl.x; q.y = xv.y + dl.y; q.z = xv.z + dl.z; q.w = xv.w + dl.w;
        ls.x = 0.25f * dl.x * dl.x; ls.y = 0.25f * dl.y * dl.y;
        ls.z = 0.25f * dl.z * dl.z; ls.w = 0.25f * dl.w * dl.w;
        lossp[i] = ls;
        qp[i]    = q;
    }

    const unsigned hot4 = idx >> 2, comp = idx & 3;
#pragma unroll
    for (int i = lane; i < NEMB / 4; i += 32) {
        float4 z = make_float4(0.f, 0.f, 0.f, 0.f);
        if ((unsigned)i == hot4) ((float*)&z)[comp] = 1.0f;
        ohp[i] = z;
    }
}

// ---------------------------------------------------------------------------
extern "C" void kernel_launch(void* const* d_in, const int* in_sizes, int n_in,
                              void* d_out, int out_size) {
    const float* x;
    const float* e;
    // metadata order: inputs (65536*256) then embedding (1024*256); be defensive.
    if (in_sizes[0] == B_ROWS * DIM) {
        x = (const float*)d_in[0];
        e = (const float*)d_in[1];
    } else {
        x = (const float*)d_in[1];
        e = (const float*)d_in[0];
    }
    float* out = (float*)d_out;

    row_norms_kernel<<<B_ROWS / 8, 256>>>(x);   // 8 warps/CTA
    emb_norms_kernel<<<NEMB / 8, 256>>>(e);

    dim3 grid(B_ROWS / TM, NEMB / TN);          // 512 x 8
    gemm_argmin_kernel<<<grid, 256>>>(x, e);

    output_kernel<<<B_ROWS / 8, 256>>>(x, e, out);
}

// round 3
// speedup vs baseline: 3.5181x; 3.5181x over previous
#include <cuda_runtime.h>
#include <cuda_bf16.h>
#include <cuda_fp16.h>
#include <cstdint>

#define B_ROWS 65536
#define DIM    256
#define NEMB   1024
#define MARGIN 2.0f

// ---------------------------------------------------------------------------
// Scratch (__device__ globals; no allocations)
// ---------------------------------------------------------------------------
__device__ float          g_xnorm[B_ROWS];
__device__ float          g_enorm[NEMB];
__device__ __nv_bfloat16  g_xb[(size_t)B_ROWS * DIM];
__device__ __nv_bfloat16  g_eb[(size_t)NEMB * DIM];
__device__ __half         g_dist_h[(size_t)B_ROWS * NEMB];   // 134 MB approx distances

// ---------------------------------------------------------------------------
// PTX helpers (arch-agnostic: sm_80+ features only)
// ---------------------------------------------------------------------------
__device__ __forceinline__ uint32_t smem_u32(const void* p) {
    uint32_t a;
    asm("{ .reg .u64 t; cvta.to.shared.u64 t, %1; cvt.u32.u64 %0, t; }" : "=r"(a) : "l"(p));
    return a;
}
__device__ __forceinline__ void cp_async16(uint32_t dst, const void* src) {
    asm volatile("cp.async.cg.shared.global [%0], [%1], 16;" :: "r"(dst), "l"(src));
}
#define CP_COMMIT() asm volatile("cp.async.commit_group;" ::: "memory")
#define CP_WAIT(n)  asm volatile("cp.async.wait_group %0;" :: "n"(n) : "memory")

__device__ __forceinline__ void ldsm_x4(uint32_t* r, uint32_t addr) {
    asm volatile("ldmatrix.sync.aligned.m8n8.x4.shared.b16 {%0,%1,%2,%3}, [%4];"
                 : "=r"(r[0]), "=r"(r[1]), "=r"(r[2]), "=r"(r[3]) : "r"(addr) : "memory");
}
__device__ __forceinline__ void mma_bf16(float* c, const uint32_t* a, const uint32_t* b) {
    asm volatile("mma.sync.aligned.m16n8k16.row.col.f32.bf16.bf16.f32 "
                 "{%0,%1,%2,%3}, {%4,%5,%6,%7}, {%8,%9}, {%0,%1,%2,%3};"
                 : "+f"(c[0]), "+f"(c[1]), "+f"(c[2]), "+f"(c[3])
                 : "r"(a[0]), "r"(a[1]), "r"(a[2]), "r"(a[3]), "r"(b[0]), "r"(b[1]));
}

// ---------------------------------------------------------------------------
// Prep: fp32 -> bf16 conversion + row norms (one warp per row)
// ---------------------------------------------------------------------------
__global__ void prep_x_kernel(const float* __restrict__ x) {
    int m = blockIdx.x * 8 + (threadIdx.x >> 5);
    int lane = threadIdx.x & 31;
    const float4* xr = (const float4*)(x + (size_t)m * DIM);
    uint2* xb = (uint2*)(g_xb + (size_t)m * DIM);
    float s = 0.f;
#pragma unroll
    for (int i = 0; i < 2; i++) {
        int f = lane + i * 32;
        float4 v = xr[f];
        s += v.x * v.x + v.y * v.y + v.z * v.z + v.w * v.w;
        __nv_bfloat162 lo = __floats2bfloat162_rn(v.x, v.y);
        __nv_bfloat162 hi = __floats2bfloat162_rn(v.z, v.w);
        uint2 pk;
        pk.x = *(unsigned*)&lo; pk.y = *(unsigned*)&hi;
        xb[f] = pk;
    }
#pragma unroll
    for (int o = 16; o; o >>= 1) s += __shfl_xor_sync(0xFFFFFFFFu, s, o);
    if (lane == 0) g_xnorm[m] = s;
}

__global__ void prep_e_kernel(const float* __restrict__ e) {
    int m = blockIdx.x * 8 + (threadIdx.x >> 5);
    int lane = threadIdx.x & 31;
    const float4* er = (const float4*)(e + (size_t)m * DIM);
    uint2* eb = (uint2*)(g_eb + (size_t)m * DIM);
    float s = 0.f;
#pragma unroll
    for (int i = 0; i < 2; i++) {
        int f = lane + i * 32;
        float4 v = er[f];
        s += v.x * v.x + v.y * v.y + v.z * v.z + v.w * v.w;
        __nv_bfloat162 lo = __floats2bfloat162_rn(v.x, v.y);
        __nv_bfloat162 hi = __floats2bfloat162_rn(v.z, v.w);
        uint2 pk;
        pk.x = *(unsigned*)&lo; pk.y = *(unsigned*)&hi;
        eb[f] = pk;
    }
#pragma unroll
    for (int o = 16; o; o >>= 1) s += __shfl_xor_sync(0xFFFFFFFFu, s, o);
    if (lane == 0) g_enorm[m] = s;
}

// ---------------------------------------------------------------------------
// HMMA GEMM: approx distances.
// Grid = 512 CTAs (one per 128-row M block). A tile SMEM-resident (loaded once);
// loop over 8 N-blocks of 128 codes, cp.async double-buffered B.
// 8 warps, 2(M)x4(N) layout, warp tile 64x32 via mma.m16n8k16 bf16->fp32.
// SMEM bf16 tiles: row = 512B (256 bf16), 16B chunk c stored at c ^ (row&7)
// -> conflict-free ldmatrix + conflict-free cp.async stores.
// Epilogue stores fp16 distances d = xn + en - 2*dot.
// ---------------------------------------------------------------------------
#define SMEM_A_OFF  0
#define SMEM_B_OFF  65536
#define SMEM_EN_OFF 196608
#define SMEM_XN_OFF 200704
#define GEMM_SMEM   201216

__global__ __launch_bounds__(256, 1) void gemm_dist_kernel() {
    extern __shared__ char smem[];
    const uint32_t sb = smem_u32(smem);
    const int tid = threadIdx.x, lane = tid & 31, wid = tid >> 5;
    const int warp_m = wid >> 2, warp_n = wid & 3;
    const int m0 = blockIdx.x * 128;

    float* s_en = (float*)(smem + SMEM_EN_OFF);
    float* s_xn = (float*)(smem + SMEM_XN_OFF);
    for (int i = tid; i < NEMB; i += 256) s_en[i] = g_enorm[i];
    if (tid < 128) s_xn[tid] = g_xnorm[m0 + tid];

    // A tile + B block 0 (group 0), B block 1 (group 1)
    {
        const __nv_bfloat16* Asrc = g_xb + (size_t)m0 * DIM;
        for (int i = tid; i < 4096; i += 256) {
            int row = i >> 5, c = i & 31;
            cp_async16(sb + SMEM_A_OFF + row * 512 + ((c ^ (row & 7)) * 16),
                       Asrc + row * DIM + c * 8);
        }
        for (int i = tid; i < 4096; i += 256) {
            int row = i >> 5, c = i & 31;
            cp_async16(sb + SMEM_B_OFF + row * 512 + ((c ^ (row & 7)) * 16),
                       g_eb + row * DIM + c * 8);
        }
        CP_COMMIT();
        for (int i = tid; i < 4096; i += 256) {
            int row = i >> 5, c = i & 31;
            cp_async16(sb + SMEM_B_OFF + 65536 + row * 512 + ((c ^ (row & 7)) * 16),
                       g_eb + 128 * DIM + row * DIM + c * 8);
        }
        CP_COMMIT();
    }

    const int grp = lane >> 2, qc = (lane & 3) * 2;

#pragma unroll 1
    for (int nb = 0; nb < 8; nb++) {
        if (nb < 7) { CP_WAIT(1); } else { CP_WAIT(0); }
        __syncthreads();

        const uint32_t Abase = sb + SMEM_A_OFF;
        const uint32_t Bbase = sb + SMEM_B_OFF + (nb & 1) * 65536;

        float acc[4][4][4];
#pragma unroll
        for (int t = 0; t < 4; t++)
#pragma unroll
            for (int u = 0; u < 4; u++)
#pragma unroll
                for (int v = 0; v < 4; v++) acc[t][u][v] = 0.f;

#pragma unroll
        for (int ks = 0; ks < 16; ks++) {
            uint32_t a[4][4];
#pragma unroll
            for (int t = 0; t < 4; t++) {
                int row = warp_m * 64 + t * 16 + (lane & 15);
                int c = ks * 2 + (lane >> 4);
                ldsm_x4(a[t], Abase + row * 512 + ((c ^ (row & 7)) * 16));
            }
            uint32_t b[2][4];
#pragma unroll
            for (int p = 0; p < 2; p++) {
                int row = warp_n * 32 + p * 16 + (lane & 7) + ((lane >> 4) & 1) * 8;
                int c = ks * 2 + ((lane >> 3) & 1);
                ldsm_x4(b[p], Bbase + row * 512 + ((c ^ (row & 7)) * 16));
            }
#pragma unroll
            for (int t = 0; t < 4; t++)
#pragma unroll
                for (int u = 0; u < 4; u++)
                    mma_bf16(acc[t][u], a[t], &b[u >> 1][(u & 1) * 2]);
        }
        __syncthreads();   // all warps done reading this B buffer

        // Prefetch B block nb+2 into the buffer just freed.
        if (nb + 2 < 8) {
            const __nv_bfloat16* Bsrc = g_eb + (size_t)(nb + 2) * 128 * DIM;
            uint32_t Bdst = sb + SMEM_B_OFF + (nb & 1) * 65536;
            for (int i = tid; i < 4096; i += 256) {
                int row = i >> 5, c = i & 31;
                cp_async16(Bdst + row * 512 + ((c ^ (row & 7)) * 16),
                           Bsrc + row * DIM + c * 8);
            }
            CP_COMMIT();
        }

        // Epilogue: distances -> fp16 (overlaps with prefetch).
#pragma unroll
        for (int t = 0; t < 4; t++) {
            int r0 = warp_m * 64 + t * 16 + grp;
            int r1 = r0 + 8;
            float xn0 = s_xn[r0], xn1 = s_xn[r1];
#pragma unroll
            for (int u = 0; u < 4; u++) {
                int ng = nb * 128 + warp_n * 32 + u * 8 + qc;
                float en0 = s_en[ng], en1 = s_en[ng + 1];
                float d0 = fmaf(-2.f, acc[t][u][0], xn0 + en0);
                float d1 = fmaf(-2.f, acc[t][u][1], xn0 + en1);
                float d2 = fmaf(-2.f, acc[t][u][2], xn1 + en0);
                float d3 = fmaf(-2.f, acc[t][u][3], xn1 + en1);
                *(__half2*)(g_dist_h + (size_t)(m0 + r0) * NEMB + ng) = __floats2half2_rn(d0, d1);
                *(__half2*)(g_dist_h + (size_t)(m0 + r1) * NEMB + ng) = __floats2half2_rn(d2, d3);
            }
        }
    }
}

// ---------------------------------------------------------------------------
// Select + refine + outputs. One warp per row.
// fp16 approx dists -> approx min -> candidates within MARGIN -> exact fp32
// distances for candidates -> final argmin -> outputs.
// ---------------------------------------------------------------------------
__global__ __launch_bounds__(256) void select_output_kernel(const float* __restrict__ x,
                                                            const float* __restrict__ Emb,
                                                            float* __restrict__ out) {
    const int wid = threadIdx.x >> 5, lane = threadIdx.x & 31;
    const int m = blockIdx.x * 8 + wid;

    __shared__ int s_cnt[8];
    __shared__ int s_cand[8][16];
    if (lane == 0) s_cnt[wid] = 0;
    __syncwarp();

    // Row's 1024 fp16 distances: 4 x uint4 per lane (8 halves each).
    const uint4* dp = (const uint4*)(g_dist_h + (size_t)m * NEMB);
    uint4 dv[4];
    unsigned long long bk = 0xFFFFFFFFFFFFFFFFULL;
#pragma unroll
    for (int i = 0; i < 4; i++) {
        int f = lane + i * 32;
        dv[i] = dp[f];
#pragma unroll
        for (int c = 0; c < 4; c++) {
            float2 f2 = __half22float2(((const __half2*)&dv[i])[c]);
            int col = f * 8 + c * 2;
            float v0 = fmaxf(f2.x, 0.f), v1 = fmaxf(f2.y, 0.f);
            unsigned long long k0 = ((unsigned long long)__float_as_uint(v0) << 32) | (unsigned)col;
            unsigned long long k1 = ((unsigned long long)__float_as_uint(v1) << 32) | (unsigned)(col + 1);
            bk = k0 < bk ? k0 : bk;
            bk = k1 < bk ? k1 : bk;
        }
    }
#pragma unroll
    for (int o = 16; o; o >>= 1) {
        unsigned long long t = __shfl_xor_sync(0xFFFFFFFFu, bk, o);
        bk = t < bk ? t : bk;
    }
    const float thr = __uint_as_float((unsigned)(bk >> 32)) + MARGIN;

    // Collect candidates within margin.
#pragma unroll
    for (int i = 0; i < 4; i++) {
        int f = lane + i * 32;
#pragma unroll
        for (int c = 0; c < 4; c++) {
            float2 f2 = __half22float2(((const __half2*)&dv[i])[c]);
            int col = f * 8 + c * 2;
            if (f2.x <= thr) {
                int pos = atomicAdd(&s_cnt[wid], 1);
                if (pos < 16) s_cand[wid][pos] = col;
            }
            if (f2.y <= thr) {
                int pos = atomicAdd(&s_cnt[wid], 1);
                if (pos < 16) s_cand[wid][pos] = col + 1;
            }
        }
    }
    __syncwarp();
    const int cnt = s_cnt[wid];
    const bool fallback = cnt > 16;      // astronomically rare; exact full scan
    const int ncand = fallback ? NEMB : cnt;

    const float4* xr = (const float4*)(x + (size_t)m * DIM);
    float4 xv0 = xr[lane], xv1 = xr[lane + 32];
    const float xn = g_xnorm[m];

    unsigned long long best = 0xFFFFFFFFFFFFFFFFULL;
    for (int t = 0; t < ncand; t++) {
        const int col = fallback ? t : s_cand[wid][t];
        const float4* er = (const float4*)(Emb + (size_t)col * DIM);
        float4 e0 = er[lane], e1 = er[lane + 32];
        float p = 0.f;
        p = fmaf(xv0.x, e0.x, p); p = fmaf(xv0.y, e0.y, p);
        p = fmaf(xv0.z, e0.z, p); p = fmaf(xv0.w, e0.w, p);
        p = fmaf(xv1.x, e1.x, p); p = fmaf(xv1.y, e1.y, p);
        p = fmaf(xv1.z, e1.z, p); p = fmaf(xv1.w, e1.w, p);
#pragma unroll
        for (int o = 16; o; o >>= 1) p += __shfl_xor_sync(0xFFFFFFFFu, p, o);
        float d = fmaxf(xn + g_enorm[col] - 2.f * p, 0.f);
        unsigned long long key = ((unsigned long long)__float_as_uint(d) << 32) | (unsigned)col;
        best = key < best ? key : best;
    }
    const unsigned idx = (unsigned)(best & 0xFFFFFFFFULL);

    // Outputs: loss | quantized_st | onehot.
    const float4* er = (const float4*)(Emb + (size_t)idx * DIM);
    float4* lossp = (float4*)out + (size_t)m * (DIM / 4);
    float4* qp    = (float4*)(out + (size_t)B_ROWS * DIM) + (size_t)m * (DIM / 4);
    float4* ohp   = (float4*)(out + 2ull * B_ROWS * DIM) + (size_t)m * (NEMB / 4);

#pragma unroll
    for (int i = 0; i < 2; i++) {
        int f = lane + i * 32;
        float4 xvv = (i == 0) ? xv0 : xv1;
        float4 ev = er[f];
        float4 dl, ls, q;
        dl.x = ev.x - xvv.x; dl.y = ev.y - xvv.y; dl.z = ev.z - xvv.z; dl.w = ev.w - xvv.w;
        q.x = xvv.x + dl.x; q.y = xvv.y + dl.y; q.z = xvv.z + dl.z; q.w = xvv.w + dl.w;
        ls.x = 0.25f * dl.x * dl.x; ls.y = 0.25f * dl.y * dl.y;
        ls.z = 0.25f * dl.z * dl.z; ls.w = 0.25f * dl.w * dl.w;
        lossp[f] = ls;
        qp[f] = q;
    }
    const unsigned hot4 = idx >> 2, comp = idx & 3;
#pragma unroll
    for (int i = lane; i < NEMB / 4; i += 32) {
        float4 z = make_float4(0.f, 0.f, 0.f, 0.f);
        if ((unsigned)i == hot4) ((float*)&z)[comp] = 1.0f;
        ohp[i] = z;
    }
}

// ---------------------------------------------------------------------------
extern "C" void kernel_launch(void* const* d_in, const int* in_sizes, int n_in,
                              void* d_out, int out_size) {
    const float* x;
    const float* e;
    if (in_sizes[0] == B_ROWS * DIM) {
        x = (const float*)d_in[0];
        e = (const float*)d_in[1];
    } else {
        x = (const float*)d_in[1];
        e = (const float*)d_in[0];
    }
    float* out = (float*)d_out;

    static bool attr_done = false;
    if (!attr_done) {
        cudaFuncSetAttribute(gemm_dist_kernel,
                             cudaFuncAttributeMaxDynamicSharedMemorySize, GEMM_SMEM);
        attr_done = true;
    }

    prep_x_kernel<<<B_ROWS / 8, 256>>>(x);
    prep_e_kernel<<<NEMB / 8, 256>>>(e);

    gemm_dist_kernel<<<B_ROWS / 128, 256, GEMM_SMEM>>>();

    select_output_kernel<<<B_ROWS / 8, 256>>>(x, e, out);
}